// round 8
// baseline (speedup 1.0000x reference)
#include <cuda_runtime.h>
#include <cstdint>

// ---------------- scratch ---------------------------------------------------
__device__ float g_adj[32 * 256 * 256];        // binary adjacency (diag forced 1)
__device__ float g_inv[32 * 256];              // 1 / rowsum
__device__ float g_G[32 * 4 * 256 * 256];      // features @ Wl + bl (tf32-rounded bits)

#define TBL 32768
#define CMAX 160.0f
#define TSCALE ((float)TBL / (2.0f * CMAX))
#define GUARD 4e-3f
__device__ float g_dz[TBL + 1];                // z0-z1 as a function of corr

// ---------------- JAX threefry2x32, key = (0, 42), partitionable -----------
__device__ __forceinline__ uint32_t rotl32(uint32_t x, int d) {
    return (x << d) | (x >> (32 - d));
}

__device__ __forceinline__ void threefry2x32(uint32_t x0, uint32_t x1,
                                             uint32_t& o0, uint32_t& o1) {
    const uint32_t k0 = 0u, k1 = 42u, k2 = 0x1BD11BF0u;
    x0 += k0; x1 += k1;
#define TF_R(r) { x0 += x1; x1 = rotl32(x1, (r)); x1 ^= x0; }
    TF_R(13) TF_R(15) TF_R(26) TF_R(6)
    x0 += k1; x1 += k2 + 1u;
    TF_R(17) TF_R(29) TF_R(16) TF_R(24)
    x0 += k2; x1 += k0 + 2u;
    TF_R(13) TF_R(15) TF_R(26) TF_R(6)
    x0 += k0; x1 += k1 + 3u;
    TF_R(17) TF_R(29) TF_R(16) TF_R(24)
    x0 += k1; x1 += k2 + 4u;
    TF_R(13) TF_R(15) TF_R(26) TF_R(6)
    x0 += k2; x1 += k0 + 5u;
#undef TF_R
    o0 = x0; o1 = x1;
}

__device__ __forceinline__ uint32_t tf_bits(uint32_t flat_idx) {
    uint32_t o0, o1;
    threefry2x32(0u, flat_idx, o0, o1);
    return o0 ^ o1;
}

__device__ __forceinline__ float gumbel_from_bits(uint32_t bits) {
    float f = __uint_as_float((bits >> 9) | 0x3f800000u) - 1.0f;
    float u = fmaxf(1e-10f, f + 1e-10f);
    return -__logf(-__logf(u));
}

__device__ __forceinline__ float gelu_exact(float x) {
    return 0.5f * x * (1.0f + erff(x * 0.70710678118654752440f));
}

__device__ float2 mlp_z(float corr,
                        const float* W1, const float* b1,
                        const float* W2, const float* b2,
                        const float* W3, const float* b3) {
    float h1[16];
#pragma unroll
    for (int a = 0; a < 16; a++)
        h1[a] = gelu_exact(fmaf(corr, W1[a], b1[a]));
    float z0 = b3[0], z1 = b3[1];
#pragma unroll
    for (int c = 0; c < 8; c++) {
        float acc2 = b2[c];
#pragma unroll
        for (int a = 0; a < 16; a++)
            acc2 = fmaf(h1[a], W2[a * 8 + c], acc2);
        float h2 = gelu_exact(acc2);
        z0 = fmaf(h2, W3[c * 2 + 0], z0);
        z1 = fmaf(h2, W3[c * 2 + 1], z1);
    }
    return make_float2(z0, z1);
}

__device__ __noinline__ float mlp_decide(float corr, float g0, float g1,
                                         const float* W1, const float* b1,
                                         const float* W2, const float* b2,
                                         const float* W3, const float* b3) {
    float2 z = mlp_z(corr, W1, b1, W2, b2, W3, b3);
    return (z.x + g0 >= z.y + g1) ? 1.0f : 0.0f;
}

// ---------------- Kernel 0: build the dz table -----------------------------
__global__ void build_dz_kernel(const float* __restrict__ W1, const float* __restrict__ b1,
                                const float* __restrict__ W2, const float* __restrict__ b2,
                                const float* __restrict__ W3, const float* __restrict__ b3) {
    int i = blockIdx.x * blockDim.x + threadIdx.x;
    if (i > TBL) return;
    float corr = -CMAX + (float)i * (2.0f * CMAX / (float)TBL);
    float2 z = mlp_z(corr, W1, b1, W2, b2, W3, b3);
    g_dz[i] = z.x - z.y;
}

// ---------------- Kernel 1: corr = fm @ fm^T (128x128 FFMA), LUT -> adj ----
__global__ __launch_bounds__(256) void corr_adj_kernel(
        const float* __restrict__ fm,
        const float* __restrict__ W1, const float* __restrict__ b1,
        const float* __restrict__ W2, const float* __restrict__ b2,
        const float* __restrict__ W3, const float* __restrict__ b3) {
    __shared__ float As[2][8][128];   // As[buf][k][s-local]
    __shared__ float Bs[2][8][128];   // Bs[buf][k][t-local]
    __shared__ float sW1[16], sb1[16], sW2[128], sb2[8], sW3[16], sb3[2];

    const int tid = threadIdx.x;
    if (tid < 16) { sW1[tid] = W1[tid]; sb1[tid] = b1[tid]; sW3[tid] = W3[tid]; }
    if (tid >= 32 && tid < 160)  sW2[tid - 32]  = W2[tid - 32];
    if (tid >= 160 && tid < 168) sb2[tid - 160] = b2[tid - 160];
    if (tid >= 168 && tid < 170) sb3[tid - 168] = b3[tid - 168];

    const int b  = blockIdx.z;
    const int s0 = blockIdx.y * 128;
    const int t0 = blockIdx.x * 128;
    const float* base = fm + (b << 16);
    const int tx = tid & 15, ty = tid >> 4;
    const int lar = tid >> 1, lac = (tid & 1) * 4;

    float acc[8][8] = {};

    // prologue: tile kk=0
    float4 va = *(const float4*)(base + (s0 + lar) * 256 + lac);
    float4 vb = *(const float4*)(base + (t0 + lar) * 256 + lac);
    As[0][lac + 0][lar] = va.x; As[0][lac + 1][lar] = va.y;
    As[0][lac + 2][lar] = va.z; As[0][lac + 3][lar] = va.w;
    Bs[0][lac + 0][lar] = vb.x; Bs[0][lac + 1][lar] = vb.y;
    Bs[0][lac + 2][lar] = vb.z; Bs[0][lac + 3][lar] = vb.w;
    __syncthreads();

    int buf = 0;
    for (int kk = 0; kk < 256; kk += 8) {
        const bool hn = (kk + 8) < 256;
        if (hn) {
            va = *(const float4*)(base + (s0 + lar) * 256 + kk + 8 + lac);
            vb = *(const float4*)(base + (t0 + lar) * 256 + kk + 8 + lac);
        }
#pragma unroll
        for (int k = 0; k < 8; k++) {
            float ar[8], br[8];
#pragma unroll
            for (int i = 0; i < 8; i++) ar[i] = As[buf][k][ty + 16 * i];
#pragma unroll
            for (int j = 0; j < 8; j++) br[j] = Bs[buf][k][tx + 16 * j];
#pragma unroll
            for (int i = 0; i < 8; i++)
#pragma unroll
                for (int j = 0; j < 8; j++)
                    acc[i][j] = fmaf(ar[i], br[j], acc[i][j]);
        }
        if (hn) {
            int nb2 = buf ^ 1;
            As[nb2][lac + 0][lar] = va.x; As[nb2][lac + 1][lar] = va.y;
            As[nb2][lac + 2][lar] = va.z; As[nb2][lac + 3][lar] = va.w;
            Bs[nb2][lac + 0][lar] = vb.x; Bs[nb2][lac + 1][lar] = vb.y;
            Bs[nb2][lac + 2][lar] = vb.z; Bs[nb2][lac + 3][lar] = vb.w;
            __syncthreads();
            buf = nb2;
        }
    }

    // epilogue: decide adjacency per entry
#pragma unroll
    for (int i = 0; i < 8; i++) {
#pragma unroll
        for (int j = 0; j < 8; j++) {
            int s = s0 + ty + 16 * i;
            int t = t0 + tx + 16 * j;
            float corr = acc[i][j];

            uint32_t st  = (uint32_t)(s * 256 + t);
            uint32_t idx = ((uint32_t)b << 17) | (st << 1);
            float g0 = gumbel_from_bits(tf_bits(idx));
            float g1 = gumbel_from_bits(tf_bits(idx + 1u));
            float gm = g1 - g0;

            float v;
            float x = (corr + CMAX) * TSCALE;
            if (x >= 0.0f && x < (float)TBL) {
                float fx = floorf(x);
                int   ix = (int)fx;
                float fr = x - fx;
                float d0 = __ldg(&g_dz[ix]);
                float d1 = __ldg(&g_dz[ix + 1]);
                float dz = fmaf(d1 - d0, fr, d0);
                float m  = dz - gm;
                if (fabsf(m) > GUARD) {
                    v = (m >= 0.0f) ? 1.0f : 0.0f;
                } else {
                    v = mlp_decide(corr, g0, g1, sW1, sb1, sW2, sb2, sW3, sb3);
                }
            } else {
                v = mlp_decide(corr, g0, g1, sW1, sb1, sW2, sb2, sW3, sb3);
            }

            if (s == t) v = 1.0f;
            g_adj[(b << 16) + (s << 8) + t] = v;
        }
    }
}

// ---------------- Kernel 2: row sums -> 1/sum ------------------------------
__global__ void rowinv_kernel() {
    int warp = (blockIdx.x * blockDim.x + threadIdx.x) >> 5;
    int lane = threadIdx.x & 31;
    const float* row = g_adj + warp * 256;
    float s = 0.0f;
#pragma unroll
    for (int t = 0; t < 256; t += 32) s += row[t + lane];
#pragma unroll
    for (int o = 16; o > 0; o >>= 1) s += __shfl_xor_sync(0xffffffffu, s, o);
    if (lane == 0) g_inv[warp] = 1.0f / s;
}

// ---------------- tf32 mma helpers -----------------------------------------
__device__ __forceinline__ uint32_t f2tf(float x) {
    uint32_t r;
    asm("cvt.rna.tf32.f32 %0, %1;" : "=r"(r) : "f"(x));
    return r;
}

__device__ __forceinline__ void mma_tf32(float* d, const uint32_t* a, const uint32_t* b) {
    asm("mma.sync.aligned.m16n8k8.row.col.f32.tf32.tf32.f32 "
        "{%0,%1,%2,%3},{%4,%5,%6,%7},{%8,%9},{%0,%1,%2,%3};"
        : "+f"(d[0]), "+f"(d[1]), "+f"(d[2]), "+f"(d[3])
        : "r"(a[0]), "r"(a[1]), "r"(a[2]), "r"(a[3]), "r"(b[0]), "r"(b[1]));
}

// ---------------- Kernel 3: G = features @ Wl + bl (tf32, double-buffered) -
// Stores g_G tf32-rounded so gemm_out needs no cvt.
__global__ __launch_bounds__(256) void gemm_G_tf32(const float* __restrict__ A,
                                                   const float* __restrict__ Bm,
                                                   const float* __restrict__ bl) {
    __shared__ uint32_t As[2][128][20];
    __shared__ uint32_t Bs[2][16][136];

    const int tid  = threadIdx.x;
    const int lane = tid & 31;
    const int g    = lane >> 2;
    const int tg   = lane & 3;
    const int warp = tid >> 5;
    const int wr   = warp >> 2;
    const int wc   = warp & 3;
    const int m0   = blockIdx.y * 128;
    const int n0   = blockIdx.x * 128;

    const int am = tid >> 2,  as = (tid & 3) * 4;    // A: fa=tid   -> rows 0..63
    const int am2 = am + 64;                          //    fa=tid+256 -> rows 64..127
    const int bk = tid >> 5,  bs = (tid & 31) * 4;   // B: fb=tid   -> k 0..7
    const int bk2 = bk + 8;                           //    fb=tid+256 -> k 8..15

    float4 sa0, sa1, sb0, sb1;

    // prologue: tile kk=0 (raw fp32)
    sa0 = *(const float4*)(A + (m0 + am) * 256 + as);
    sa1 = *(const float4*)(A + (m0 + am2) * 256 + as);
    sb0 = *(const float4*)(Bm + bk * 256 + n0 + bs);
    sb1 = *(const float4*)(Bm + bk2 * 256 + n0 + bs);
    *(uint4*)&As[0][am][as]  = make_uint4(f2tf(sa0.x), f2tf(sa0.y), f2tf(sa0.z), f2tf(sa0.w));
    *(uint4*)&As[0][am2][as] = make_uint4(f2tf(sa1.x), f2tf(sa1.y), f2tf(sa1.z), f2tf(sa1.w));
    *(uint4*)&Bs[0][bk][bs]  = make_uint4(f2tf(sb0.x), f2tf(sb0.y), f2tf(sb0.z), f2tf(sb0.w));
    *(uint4*)&Bs[0][bk2][bs] = make_uint4(f2tf(sb1.x), f2tf(sb1.y), f2tf(sb1.z), f2tf(sb1.w));
    __syncthreads();

    float acc[4][4][4] = {};
    int buf = 0;

    for (int kk = 0; kk < 256; kk += 16) {
        const bool hn = (kk + 16) < 256;
        if (hn) {
            sa0 = *(const float4*)(A + (m0 + am) * 256 + kk + 16 + as);
            sa1 = *(const float4*)(A + (m0 + am2) * 256 + kk + 16 + as);
            sb0 = *(const float4*)(Bm + (kk + 16 + bk) * 256 + n0 + bs);
            sb1 = *(const float4*)(Bm + (kk + 16 + bk2) * 256 + n0 + bs);
        }
#pragma unroll
        for (int ks = 0; ks < 16; ks += 8) {
            uint32_t afr[4][4], bfr[4][2];
#pragma unroll
            for (int mi = 0; mi < 4; mi++) {
                int m = wr * 64 + mi * 16 + g;
                afr[mi][0] = As[buf][m][ks + tg];
                afr[mi][1] = As[buf][m + 8][ks + tg];
                afr[mi][2] = As[buf][m][ks + tg + 4];
                afr[mi][3] = As[buf][m + 8][ks + tg + 4];
            }
#pragma unroll
            for (int ni = 0; ni < 4; ni++) {
                int n = wc * 32 + ni * 8 + g;
                bfr[ni][0] = Bs[buf][ks + tg][n];
                bfr[ni][1] = Bs[buf][ks + tg + 4][n];
            }
#pragma unroll
            for (int mi = 0; mi < 4; mi++)
#pragma unroll
                for (int ni = 0; ni < 4; ni++)
                    mma_tf32(acc[mi][ni], afr[mi], bfr[ni]);
        }
        if (hn) {
            int nb2 = buf ^ 1;
            *(uint4*)&As[nb2][am][as]  = make_uint4(f2tf(sa0.x), f2tf(sa0.y), f2tf(sa0.z), f2tf(sa0.w));
            *(uint4*)&As[nb2][am2][as] = make_uint4(f2tf(sa1.x), f2tf(sa1.y), f2tf(sa1.z), f2tf(sa1.w));
            *(uint4*)&Bs[nb2][bk][bs]  = make_uint4(f2tf(sb0.x), f2tf(sb0.y), f2tf(sb0.z), f2tf(sb0.w));
            *(uint4*)&Bs[nb2][bk2][bs] = make_uint4(f2tf(sb1.x), f2tf(sb1.y), f2tf(sb1.z), f2tf(sb1.w));
            __syncthreads();
            buf = nb2;
        }
    }

    // epilogue: + bl, store tf32-rounded bits
#pragma unroll
    for (int mi = 0; mi < 4; mi++) {
        int r0 = m0 + wr * 64 + mi * 16 + g;
#pragma unroll
        for (int ni = 0; ni < 4; ni++) {
            int c0 = n0 + wc * 32 + ni * 8 + tg * 2;
            float bl0 = __ldg(bl + c0), bl1 = __ldg(bl + c0 + 1);
            g_G[r0 * 256 + c0]           = __uint_as_float(f2tf(acc[mi][ni][0] + bl0));
            g_G[r0 * 256 + c0 + 1]       = __uint_as_float(f2tf(acc[mi][ni][1] + bl1));
            g_G[(r0 + 8) * 256 + c0]     = __uint_as_float(f2tf(acc[mi][ni][2] + bl0));
            g_G[(r0 + 8) * 256 + c0 + 1] = __uint_as_float(f2tf(acc[mi][ni][3] + bl1));
        }
    }
}

// ---------------- Kernel 4: out = (adj/rowsum) @ G (tf32, double-buffered) -
// adj is exactly 0/1 (tf32-exact), g_G pre-rounded -> zero cvts.
__global__ __launch_bounds__(256) void gemm_out_tf32(float* __restrict__ out) {
    __shared__ uint32_t As[2][128][20];
    __shared__ uint32_t Bs[2][16][136];

    const int tid  = threadIdx.x;
    const int lane = tid & 31;
    const int g    = lane >> 2;
    const int tg   = lane & 3;
    const int warp = tid >> 5;
    const int wr   = warp >> 2;
    const int wc   = warp & 3;
    const int z    = blockIdx.z;          // b*4 + c
    const int b    = z >> 2;
    const int m0   = blockIdx.y * 128;
    const int n0   = blockIdx.x * 128;

    const uint32_t* A  = (const uint32_t*)(g_adj) + (b << 16);
    const uint32_t* Bm = (const uint32_t*)(g_G) + (z << 16);

    const int am = tid >> 2,  as = (tid & 3) * 4;
    const int am2 = am + 64;
    const int bk = tid >> 5,  bs = (tid & 31) * 4;
    const int bk2 = bk + 8;

    uint4 sa0, sa1, sb0, sb1;

    sa0 = *(const uint4*)(A + (m0 + am) * 256 + as);
    sa1 = *(const uint4*)(A + (m0 + am2) * 256 + as);
    sb0 = *(const uint4*)(Bm + bk * 256 + n0 + bs);
    sb1 = *(const uint4*)(Bm + bk2 * 256 + n0 + bs);
    *(uint4*)&As[0][am][as]  = sa0;
    *(uint4*)&As[0][am2][as] = sa1;
    *(uint4*)&Bs[0][bk][bs]  = sb0;
    *(uint4*)&Bs[0][bk2][bs] = sb1;
    __syncthreads();

    float acc[4][4][4] = {};
    int buf = 0;

    for (int kk = 0; kk < 256; kk += 16) {
        const bool hn = (kk + 16) < 256;
        if (hn) {
            sa0 = *(const uint4*)(A + (m0 + am) * 256 + kk + 16 + as);
            sa1 = *(const uint4*)(A + (m0 + am2) * 256 + kk + 16 + as);
            sb0 = *(const uint4*)(Bm + (kk + 16 + bk) * 256 + n0 + bs);
            sb1 = *(const uint4*)(Bm + (kk + 16 + bk2) * 256 + n0 + bs);
        }
#pragma unroll
        for (int ks = 0; ks < 16; ks += 8) {
            uint32_t afr[4][4], bfr[4][2];
#pragma unroll
            for (int mi = 0; mi < 4; mi++) {
                int m = wr * 64 + mi * 16 + g;
                afr[mi][0] = As[buf][m][ks + tg];
                afr[mi][1] = As[buf][m + 8][ks + tg];
                afr[mi][2] = As[buf][m][ks + tg + 4];
                afr[mi][3] = As[buf][m + 8][ks + tg + 4];
            }
#pragma unroll
            for (int ni = 0; ni < 4; ni++) {
                int n = wc * 32 + ni * 8 + g;
                bfr[ni][0] = Bs[buf][ks + tg][n];
                bfr[ni][1] = Bs[buf][ks + tg + 4][n];
            }
#pragma unroll
            for (int mi = 0; mi < 4; mi++)
#pragma unroll
                for (int ni = 0; ni < 4; ni++)
                    mma_tf32(acc[mi][ni], afr[mi], bfr[ni]);
        }
        if (hn) {
            int nb2 = buf ^ 1;
            *(uint4*)&As[nb2][am][as]  = sa0;
            *(uint4*)&As[nb2][am2][as] = sa1;
            *(uint4*)&Bs[nb2][bk][bs]  = sb0;
            *(uint4*)&Bs[nb2][bk2][bs] = sb1;
            __syncthreads();
            buf = nb2;
        }
    }

#pragma unroll
    for (int mi = 0; mi < 4; mi++) {
        int r0 = m0 + wr * 64 + mi * 16 + g;
        float sc0 = g_inv[(b << 8) + r0];
        float sc1 = g_inv[(b << 8) + r0 + 8];
#pragma unroll
        for (int ni = 0; ni < 4; ni++) {
            int c0 = n0 + wc * 32 + ni * 8 + tg * 2;
            out[(z << 16) + r0 * 256 + c0]           = acc[mi][ni][0] * sc0;
            out[(z << 16) + r0 * 256 + c0 + 1]       = acc[mi][ni][1] * sc0;
            out[(z << 16) + (r0 + 8) * 256 + c0]     = acc[mi][ni][2] * sc1;
            out[(z << 16) + (r0 + 8) * 256 + c0 + 1] = acc[mi][ni][3] * sc1;
        }
    }
}

// ---------------- launch ---------------------------------------------------
extern "C" void kernel_launch(void* const* d_in, const int* in_sizes, int n_in,
                              void* d_out, int out_size) {
    const float* features = (const float*)d_in[0];  // [32,4,256,256]
    const float* fm       = (const float*)d_in[1];  // [32,256,256]
    const float* W1 = (const float*)d_in[2];
    const float* b1 = (const float*)d_in[3];
    const float* W2 = (const float*)d_in[4];
    const float* b2 = (const float*)d_in[5];
    const float* W3 = (const float*)d_in[6];
    const float* b3 = (const float*)d_in[7];
    const float* Wl = (const float*)d_in[8];
    const float* bl = (const float*)d_in[9];
    float* out = (float*)d_out;

    build_dz_kernel<<<(TBL + 256) / 256, 256>>>(W1, b1, W2, b2, W3, b3);
    corr_adj_kernel<<<dim3(2, 2, 32), 256>>>(fm, W1, b1, W2, b2, W3, b3);
    rowinv_kernel<<<1024, 256>>>();
    gemm_G_tf32<<<dim3(2, 256), 256>>>(features, Wl, bl);
    gemm_out_tf32<<<dim3(2, 2, 128), 256>>>(out);
}